// round 7
// baseline (speedup 1.0000x reference)
#include <cuda_runtime.h>
#include <cuda_fp16.h>
#include <cuda_bf16.h>

#define N_NODES   10000
#define N_EDGES   640000
#define FEATS     128
#define F4        (FEATS/4)
#define NREP      8           // counter replicas per node
#define CAP_R     40          // bucket capacity per replica
#define EPT       4           // edges per thread in scatter

#define PREP_BLOCKS 625       // 625*256 threads * 2 float4 = 320000 float4
#define SCAT_BLOCKS 625       // 625*256 threads * 4 edges  = 640000 edges

// ---------------- scratch (no allocation allowed) ----------------
// INVARIANT: g_cnt is all-zero at kernel_launch entry. Statically zero at
// module load; k_agg_gemm re-zeroes every counter it reads before exiting.
__device__ int   g_cnt[N_NODES * NREP];            // per-(node,replica) degree
__device__ int   g_srcs[N_NODES * NREP * CAP_R];   // bucketed src lists
__device__ uint2 g_xh[N_NODES * 32];               // x in fp16: 4 halfs per lane

__device__ __forceinline__ void load4(const void* p, int t, int is64, int v[EPT]) {
    if (is64) {
        const longlong2* q = (const longlong2*)p;
        longlong2 w0 = q[t * 2];
        longlong2 w1 = q[t * 2 + 1];
        v[0] = (int)w0.x; v[1] = (int)w0.y;
        v[2] = (int)w1.x; v[3] = (int)w1.y;
    } else {
        const int4* q = (const int4*)p;
        int4 w = q[t];
        v[0] = w.x; v[1] = w.y; v[2] = w.z; v[3] = w.w;
    }
}

// merged front kernel: blocks [0,625) convert x -> fp16; blocks [625,1250) scatter
__global__ void k_front(const float4* __restrict__ x4,
                        const void* __restrict__ src,
                        const void* __restrict__ dst) {
    if (blockIdx.x < PREP_BLOCKS) {
        int i = blockIdx.x * blockDim.x + threadIdx.x;
        int a = i * 2, b = i * 2 + 1;
        if (b < N_NODES * 32) {
            float4 va = x4[a];
            float4 vb = x4[b];
            __half2 a0 = __floats2half2_rn(va.x, va.y);
            __half2 a1 = __floats2half2_rn(va.z, va.w);
            __half2 b0 = __floats2half2_rn(vb.x, vb.y);
            __half2 b1 = __floats2half2_rn(vb.z, vb.w);
            uint2 wa, wb;
            wa.x = *(unsigned int*)&a0; wa.y = *(unsigned int*)&a1;
            wb.x = *(unsigned int*)&b0; wb.y = *(unsigned int*)&b1;
            g_xh[a] = wa;
            g_xh[b] = wb;
        }
        return;
    }

    int t = (blockIdx.x - PREP_BLOCKS) * blockDim.x + threadIdx.x;
    if (t >= N_EDGES / EPT) return;

    // dtype detect: first 4 words of src as int64 all in range (broadcast, L1-hit)
    const longlong2* sp = (const longlong2*)src;
    longlong2 q0 = sp[0];
    longlong2 q1 = sp[1];
    int is64 = ((unsigned long long)q0.x < N_NODES) &
               ((unsigned long long)q0.y < N_NODES) &
               ((unsigned long long)q1.x < N_NODES) &
               ((unsigned long long)q1.y < N_NODES);

    int s[EPT], d[EPT], pos[EPT], slot[EPT];
    load4(src, t, is64, s);
    load4(dst, t, is64, d);
    int rbase = (t & 1) << 2;
    #pragma unroll
    for (int k = 0; k < EPT; k++) {
        slot[k] = d[k] * NREP + (rbase | k);
        pos[k]  = atomicAdd(&g_cnt[slot[k]], 1);
    }
    #pragma unroll
    for (int k = 0; k < EPT; k++)
        if (pos[k] < CAP_R)
            g_srcs[slot[k] * CAP_R + pos[k]] = s[k];
}

// ---------------- fused aggregation + GEMM ----------------
#define SW_STRIDE 36
#define SH_STRIDE 136

__device__ __forceinline__ void acc_half4(float4& acc, uint2 w) {
    __half2 h0 = *(__half2*)&w.x;
    __half2 h1 = *(__half2*)&w.y;
    float2 f0 = __half22float2(h0);
    float2 f1 = __half22float2(h1);
    acc.x += f0.x; acc.y += f0.y; acc.z += f1.x; acc.w += f1.y;
}

__global__ void k_agg_gemm(const float4* __restrict__ x4,
                           const float*  __restrict__ W,
                           const float*  __restrict__ bias,
                           float* __restrict__ out) {
    __shared__ float shW[128 * SW_STRIDE];
    __shared__ float shH[32 * SH_STRIDE];

    int tid  = threadIdx.x;
    int lane = tid & 31;
    int wrp  = tid >> 5;
    int row0 = blockIdx.x * 32;
    const unsigned FULL = 0xFFFFFFFFu;

    // ---- Phase A: warp-per-node, chunked index fetch + shfl-broadcast gather ----
    #pragma unroll 1
    for (int r = 0; r < 4; r++) {
        int node = row0 + wrp * 4 + r;
        if (node >= N_NODES) break;

        float4 acc0 = x4[node * F4 + lane];   // self term, fp32 exact
        float4 acc1 = make_float4(0.f, 0.f, 0.f, 0.f);
        float4 acc2 = make_float4(0.f, 0.f, 0.f, 0.f);
        float4 acc3 = make_float4(0.f, 0.f, 0.f, 0.f);

        int4 c0 = *(const int4*)&g_cnt[node * NREP];
        int4 c1 = *(const int4*)&g_cnt[node * NREP + 4];
        // reset counters for next replay (this warp is the sole reader)
        if (lane < NREP) g_cnt[node * NREP + lane] = 0;

        int cnts[NREP] = {min(c0.x,CAP_R), min(c0.y,CAP_R), min(c0.z,CAP_R), min(c0.w,CAP_R),
                          min(c1.x,CAP_R), min(c1.y,CAP_R), min(c1.z,CAP_R), min(c1.w,CAP_R)};
        int total = 0;
        #pragma unroll
        for (int b = 0; b < NREP; b++) total += cnts[b];

        int slotbase = node * NREP * CAP_R;
        int nchunks = (total + 31) >> 5;

        #pragma unroll 1
        for (int ch = 0; ch < nchunks; ch++) {
            int pos = (ch << 5) + lane;
            int myidx = 0;
            if (pos < total) {
                int run = 0, rb = 0, off = 0;
                #pragma unroll
                for (int b = 0; b < NREP; b++) {
                    int nb = cnts[b];
                    bool in = (pos >= run) & (pos < run + nb);
                    if (in) { rb = b; off = pos - run; }
                    run += nb;
                }
                myidx = g_srcs[slotbase + rb * CAP_R + off];  // lane-parallel load
            }
            int n = min(32, total - (ch << 5));
            int i = 0;
            for (; i + 8 <= n; i += 8) {
                int i0 = __shfl_sync(FULL, myidx, i);
                int i1 = __shfl_sync(FULL, myidx, i + 1);
                int i2 = __shfl_sync(FULL, myidx, i + 2);
                int i3 = __shfl_sync(FULL, myidx, i + 3);
                int i4 = __shfl_sync(FULL, myidx, i + 4);
                int i5 = __shfl_sync(FULL, myidx, i + 5);
                int i6 = __shfl_sync(FULL, myidx, i + 6);
                int i7 = __shfl_sync(FULL, myidx, i + 7);
                uint2 wa = g_xh[i0 * 32 + lane];
                uint2 wb = g_xh[i1 * 32 + lane];
                uint2 wc = g_xh[i2 * 32 + lane];
                uint2 wd = g_xh[i3 * 32 + lane];
                uint2 we = g_xh[i4 * 32 + lane];
                uint2 wf = g_xh[i5 * 32 + lane];
                uint2 wg = g_xh[i6 * 32 + lane];
                uint2 wh = g_xh[i7 * 32 + lane];
                acc_half4(acc0, wa);
                acc_half4(acc1, wb);
                acc_half4(acc2, wc);
                acc_half4(acc3, wd);
                acc_half4(acc0, we);
                acc_half4(acc1, wf);
                acc_half4(acc2, wg);
                acc_half4(acc3, wh);
            }
            for (; i + 4 <= n; i += 4) {
                int i0 = __shfl_sync(FULL, myidx, i);
                int i1 = __shfl_sync(FULL, myidx, i + 1);
                int i2 = __shfl_sync(FULL, myidx, i + 2);
                int i3 = __shfl_sync(FULL, myidx, i + 3);
                uint2 wa = g_xh[i0 * 32 + lane];
                uint2 wb = g_xh[i1 * 32 + lane];
                uint2 wc = g_xh[i2 * 32 + lane];
                uint2 wd = g_xh[i3 * 32 + lane];
                acc_half4(acc0, wa);
                acc_half4(acc1, wb);
                acc_half4(acc2, wc);
                acc_half4(acc3, wd);
            }
            for (; i < n; i++) {
                int ii = __shfl_sync(FULL, myidx, i);
                uint2 wa = g_xh[ii * 32 + lane];
                acc_half4(acc0, wa);
            }
        }
        acc0.x += acc1.x; acc0.y += acc1.y; acc0.z += acc1.z; acc0.w += acc1.w;
        acc2.x += acc3.x; acc2.y += acc3.y; acc2.z += acc3.z; acc2.w += acc3.w;
        acc0.x += acc2.x; acc0.y += acc2.y; acc0.z += acc2.z; acc0.w += acc2.w;
        *(float4*)&shH[(wrp * 4 + r) * SH_STRIDE + lane * 4] = acc0;
    }
    __syncthreads();

    // ---- Phase B: GEMM 32x128 @ 128x128^T (fp32) ----
    float acc[4][4];
    #pragma unroll
    for (int i = 0; i < 4; i++)
        #pragma unroll
        for (int j = 0; j < 4; j++) acc[i][j] = 0.f;

    for (int kk = 0; kk < FEATS; kk += 32) {
        #pragma unroll
        for (int i = 0; i < 4; i++) {
            int t  = tid + i * 256;
            int rr = t >> 3;
            int c4 = (t & 7) * 4;
            float4 v = *(const float4*)&W[rr * FEATS + kk + c4];
            *(float4*)&shW[rr * SW_STRIDE + c4] = v;
        }
        __syncthreads();

        #pragma unroll
        for (int k4 = 0; k4 < 32; k4 += 4) {
            float4 ha[4], wb[4];
            #pragma unroll
            for (int ri = 0; ri < 4; ri++)
                ha[ri] = *(const float4*)&shH[(wrp * 4 + ri) * SH_STRIDE + kk + k4];
            #pragma unroll
            for (int ci = 0; ci < 4; ci++)
                wb[ci] = *(const float4*)&shW[(lane + 32 * ci) * SW_STRIDE + k4];
            #pragma unroll
            for (int ri = 0; ri < 4; ri++)
                #pragma unroll
                for (int ci = 0; ci < 4; ci++) {
                    acc[ri][ci] += ha[ri].x * wb[ci].x;
                    acc[ri][ci] += ha[ri].y * wb[ci].y;
                    acc[ri][ci] += ha[ri].z * wb[ci].z;
                    acc[ri][ci] += ha[ri].w * wb[ci].w;
                }
        }
        __syncthreads();
    }

    #pragma unroll
    for (int ri = 0; ri < 4; ri++) {
        int rr = row0 + wrp * 4 + ri;
        if (rr >= N_NODES) continue;
        #pragma unroll
        for (int ci = 0; ci < 4; ci++) {
            int c = lane + 32 * ci;
            out[rr * FEATS + c] = acc[ri][ci] + bias[c];
        }
    }
}

// ---------------- launch ----------------
extern "C" void kernel_launch(void* const* d_in, const int* in_sizes, int n_in,
                              void* d_out, int out_size) {
    const float* x    = (const float*)d_in[0];
    const void*  src  = d_in[1];
    const void*  dst  = d_in[2];
    const float* W    = (const float*)d_in[3];
    const float* bias = (const float*)d_in[4];
    float* out = (float*)d_out;

    k_front<<<PREP_BLOCKS + SCAT_BLOCKS, 256>>>((const float4*)x, src, dst);
    k_agg_gemm<<<(N_NODES + 31) / 32, 256>>>((const float4*)x, W, bias, out);
}

// round 8
// speedup vs baseline: 1.0169x; 1.0169x over previous
#include <cuda_runtime.h>
#include <cuda_fp16.h>
#include <cuda_bf16.h>

#define N_NODES   10000
#define N_EDGES   640000
#define FEATS     128
#define F4        (FEATS/4)
#define NREP      8           // counter replicas per node
#define CAP_R     40          // bucket capacity per replica
#define EPT       4           // edges per thread in scatter

#define PREP_BLOCKS 625
#define SCAT_BLOCKS 625

#define NODES_PER_BLOCK 16    // 625 blocks, 2 nodes per warp

// ---------------- scratch (no allocation allowed) ----------------
// INVARIANT: g_cnt all-zero at entry; statically zero at load, and
// k_agg_gemm re-zeroes every counter it reads.
__device__ int   g_cnt[N_NODES * NREP];
__device__ int   g_srcs[N_NODES * NREP * CAP_R];
__device__ uint2 g_xh[N_NODES * 32];               // x in fp16

__device__ __forceinline__ void load4(const void* p, int t, int is64, int v[EPT]) {
    if (is64) {
        const longlong2* q = (const longlong2*)p;
        longlong2 w0 = q[t * 2];
        longlong2 w1 = q[t * 2 + 1];
        v[0] = (int)w0.x; v[1] = (int)w0.y;
        v[2] = (int)w1.x; v[3] = (int)w1.y;
    } else {
        const int4* q = (const int4*)p;
        int4 w = q[t];
        v[0] = w.x; v[1] = w.y; v[2] = w.z; v[3] = w.w;
    }
}

// merged front kernel: blocks [0,625) convert x -> fp16; blocks [625,1250) scatter
__global__ void k_front(const float4* __restrict__ x4,
                        const void* __restrict__ src,
                        const void* __restrict__ dst) {
    if (blockIdx.x < PREP_BLOCKS) {
        int i = blockIdx.x * blockDim.x + threadIdx.x;
        int a = i * 2, b = i * 2 + 1;
        if (b < N_NODES * 32) {
            float4 va = x4[a];
            float4 vb = x4[b];
            __half2 a0 = __floats2half2_rn(va.x, va.y);
            __half2 a1 = __floats2half2_rn(va.z, va.w);
            __half2 b0 = __floats2half2_rn(vb.x, vb.y);
            __half2 b1 = __floats2half2_rn(vb.z, vb.w);
            uint2 wa, wb;
            wa.x = *(unsigned int*)&a0; wa.y = *(unsigned int*)&a1;
            wb.x = *(unsigned int*)&b0; wb.y = *(unsigned int*)&b1;
            g_xh[a] = wa;
            g_xh[b] = wb;
        }
        return;
    }

    int t = (blockIdx.x - PREP_BLOCKS) * blockDim.x + threadIdx.x;
    if (t >= N_EDGES / EPT) return;

    const longlong2* sp = (const longlong2*)src;
    longlong2 q0 = sp[0];
    longlong2 q1 = sp[1];
    int is64 = ((unsigned long long)q0.x < N_NODES) &
               ((unsigned long long)q0.y < N_NODES) &
               ((unsigned long long)q1.x < N_NODES) &
               ((unsigned long long)q1.y < N_NODES);

    int s[EPT], d[EPT], pos[EPT], slot[EPT];
    load4(src, t, is64, s);
    load4(dst, t, is64, d);
    int rbase = (t & 1) << 2;
    #pragma unroll
    for (int k = 0; k < EPT; k++) {
        slot[k] = d[k] * NREP + (rbase | k);
        pos[k]  = atomicAdd(&g_cnt[slot[k]], 1);
    }
    #pragma unroll
    for (int k = 0; k < EPT; k++)
        if (pos[k] < CAP_R)
            g_srcs[slot[k] * CAP_R + pos[k]] = s[k];
}

// ---------------- fused aggregation + GEMM (16 nodes / block) ----------------
#define SW_STRIDE 36
#define SH_STRIDE 136

__device__ __forceinline__ void acc_half4(float4& acc, uint2 w) {
    __half2 h0 = *(__half2*)&w.x;
    __half2 h1 = *(__half2*)&w.y;
    float2 f0 = __half22float2(h0);
    float2 f1 = __half22float2(h1);
    acc.x += f0.x; acc.y += f0.y; acc.z += f1.x; acc.w += f1.y;
}

// fetch this chunk's per-lane bucket index (branchless select over 8 buckets)
__device__ __forceinline__ int fetch_chunk_idx(const int cnts[NREP], int slotbase,
                                               int pos, int total) {
    int myidx = 0;
    if (pos < total) {
        int run = 0, rb = 0, off = 0;
        #pragma unroll
        for (int b = 0; b < NREP; b++) {
            int nb = cnts[b];
            bool in = (pos >= run) & (pos < run + nb);
            if (in) { rb = b; off = pos - run; }
            run += nb;
        }
        myidx = g_srcs[slotbase + rb * CAP_R + off];
    }
    return myidx;
}

__global__ void k_agg_gemm(const float4* __restrict__ x4,
                           const float*  __restrict__ W,
                           const float*  __restrict__ bias,
                           float* __restrict__ out) {
    __shared__ float shW[128 * SW_STRIDE];              // 18.4 KB
    __shared__ float shH[NODES_PER_BLOCK * SH_STRIDE];  // 8.7 KB

    int tid  = threadIdx.x;
    int lane = tid & 31;
    int wrp  = tid >> 5;
    int row0 = blockIdx.x * NODES_PER_BLOCK;
    const unsigned FULL = 0xFFFFFFFFu;

    // ---- Phase A: each warp aggregates 2 nodes, pipelined chunk gather ----
    #pragma unroll 1
    for (int r = 0; r < 2; r++) {
        int node = row0 + wrp * 2 + r;           // 10000 = 625*16: always in range

        float4 acc0 = x4[node * F4 + lane];      // self term, fp32 exact
        float4 acc1 = make_float4(0.f, 0.f, 0.f, 0.f);
        float4 acc2 = make_float4(0.f, 0.f, 0.f, 0.f);
        float4 acc3 = make_float4(0.f, 0.f, 0.f, 0.f);

        int4 c0 = *(const int4*)&g_cnt[node * NREP];
        int4 c1 = *(const int4*)&g_cnt[node * NREP + 4];
        if (lane < NREP) g_cnt[node * NREP + lane] = 0;   // reset for next replay

        int cnts[NREP] = {min(c0.x,CAP_R), min(c0.y,CAP_R), min(c0.z,CAP_R), min(c0.w,CAP_R),
                          min(c1.x,CAP_R), min(c1.y,CAP_R), min(c1.z,CAP_R), min(c1.w,CAP_R)};
        int total = 0;
        #pragma unroll
        for (int b = 0; b < NREP; b++) total += cnts[b];

        int slotbase = node * NREP * CAP_R;
        int nchunks = (total + 31) >> 5;

        // prime pipeline: fetch chunk 0 indices
        int myidx = (nchunks > 0) ? fetch_chunk_idx(cnts, slotbase, lane, total) : 0;

        #pragma unroll 1
        for (int ch = 0; ch < nchunks; ch++) {
            // issue next chunk's index load BEFORE consuming current (overlap)
            int nextidx = 0;
            if (ch + 1 < nchunks)
                nextidx = fetch_chunk_idx(cnts, slotbase, ((ch + 1) << 5) + lane, total);

            int n = min(32, total - (ch << 5));
            int i = 0;
            for (; i + 8 <= n; i += 8) {
                int i0 = __shfl_sync(FULL, myidx, i);
                int i1 = __shfl_sync(FULL, myidx, i + 1);
                int i2 = __shfl_sync(FULL, myidx, i + 2);
                int i3 = __shfl_sync(FULL, myidx, i + 3);
                int i4 = __shfl_sync(FULL, myidx, i + 4);
                int i5 = __shfl_sync(FULL, myidx, i + 5);
                int i6 = __shfl_sync(FULL, myidx, i + 6);
                int i7 = __shfl_sync(FULL, myidx, i + 7);
                uint2 wa = g_xh[i0 * 32 + lane];
                uint2 wb = g_xh[i1 * 32 + lane];
                uint2 wc = g_xh[i2 * 32 + lane];
                uint2 wd = g_xh[i3 * 32 + lane];
                uint2 we = g_xh[i4 * 32 + lane];
                uint2 wf = g_xh[i5 * 32 + lane];
                uint2 wg = g_xh[i6 * 32 + lane];
                uint2 wh = g_xh[i7 * 32 + lane];
                acc_half4(acc0, wa);
                acc_half4(acc1, wb);
                acc_half4(acc2, wc);
                acc_half4(acc3, wd);
                acc_half4(acc0, we);
                acc_half4(acc1, wf);
                acc_half4(acc2, wg);
                acc_half4(acc3, wh);
            }
            for (; i + 4 <= n; i += 4) {
                int i0 = __shfl_sync(FULL, myidx, i);
                int i1 = __shfl_sync(FULL, myidx, i + 1);
                int i2 = __shfl_sync(FULL, myidx, i + 2);
                int i3 = __shfl_sync(FULL, myidx, i + 3);
                uint2 wa = g_xh[i0 * 32 + lane];
                uint2 wb = g_xh[i1 * 32 + lane];
                uint2 wc = g_xh[i2 * 32 + lane];
                uint2 wd = g_xh[i3 * 32 + lane];
                acc_half4(acc0, wa);
                acc_half4(acc1, wb);
                acc_half4(acc2, wc);
                acc_half4(acc3, wd);
            }
            for (; i < n; i++) {
                int ii = __shfl_sync(FULL, myidx, i);
                uint2 wa = g_xh[ii * 32 + lane];
                acc_half4(acc0, wa);
            }
            myidx = nextidx;
        }
        acc0.x += acc1.x; acc0.y += acc1.y; acc0.z += acc1.z; acc0.w += acc1.w;
        acc2.x += acc3.x; acc2.y += acc3.y; acc2.z += acc3.z; acc2.w += acc3.w;
        acc0.x += acc2.x; acc0.y += acc2.y; acc0.z += acc2.z; acc0.w += acc2.w;
        *(float4*)&shH[(wrp * 2 + r) * SH_STRIDE + lane * 4] = acc0;
    }
    __syncthreads();

    // ---- Phase B: GEMM 16x128 @ 128x128^T (fp32), 2x4 register tile ----
    float acc[2][4];
    #pragma unroll
    for (int i = 0; i < 2; i++)
        #pragma unroll
        for (int j = 0; j < 4; j++) acc[i][j] = 0.f;

    for (int kk = 0; kk < FEATS; kk += 32) {
        #pragma unroll
        for (int i = 0; i < 4; i++) {
            int t  = tid + i * 256;
            int rr = t >> 3;
            int c4 = (t & 7) * 4;
            float4 v = *(const float4*)&W[rr * FEATS + kk + c4];
            *(float4*)&shW[rr * SW_STRIDE + c4] = v;
        }
        __syncthreads();

        #pragma unroll
        for (int k4 = 0; k4 < 32; k4 += 4) {
            float4 ha[2], wb[4];
            #pragma unroll
            for (int ri = 0; ri < 2; ri++)
                ha[ri] = *(const float4*)&shH[(wrp * 2 + ri) * SH_STRIDE + kk + k4];
            #pragma unroll
            for (int ci = 0; ci < 4; ci++)
                wb[ci] = *(const float4*)&shW[(lane + 32 * ci) * SW_STRIDE + k4];
            #pragma unroll
            for (int ri = 0; ri < 2; ri++)
                #pragma unroll
                for (int ci = 0; ci < 4; ci++) {
                    acc[ri][ci] += ha[ri].x * wb[ci].x;
                    acc[ri][ci] += ha[ri].y * wb[ci].y;
                    acc[ri][ci] += ha[ri].z * wb[ci].z;
                    acc[ri][ci] += ha[ri].w * wb[ci].w;
                }
        }
        __syncthreads();
    }

    #pragma unroll
    for (int ri = 0; ri < 2; ri++) {
        int rr = row0 + wrp * 2 + ri;
        #pragma unroll
        for (int ci = 0; ci < 4; ci++) {
            int c = lane + 32 * ci;
            out[rr * FEATS + c] = acc[ri][ci] + bias[c];
        }
    }
}

// ---------------- launch ----------------
extern "C" void kernel_launch(void* const* d_in, const int* in_sizes, int n_in,
                              void* d_out, int out_size) {
    const float* x    = (const float*)d_in[0];
    const void*  src  = d_in[1];
    const void*  dst  = d_in[2];
    const float* W    = (const float*)d_in[3];
    const float* bias = (const float*)d_in[4];
    float* out = (float*)d_out;

    k_front<<<PREP_BLOCKS + SCAT_BLOCKS, 256>>>((const float4*)x, src, dst);
    k_agg_gemm<<<N_NODES / NODES_PER_BLOCK, 256>>>((const float4*)x, W, bias, out);
}

// round 9
// speedup vs baseline: 1.0394x; 1.0222x over previous
#include <cuda_runtime.h>
#include <cuda_fp16.h>
#include <cuda_bf16.h>

#define N_NODES   10000
#define N_EDGES   640000
#define FEATS     128
#define F4        (FEATS/4)
#define NREP      8           // counter replicas per node
#define CAP_R     40          // bucket capacity per replica
#define EPT       4           // edges per thread in scatter

#define PREP_BLOCKS 625
#define SCAT_BLOCKS 625

#define NODES_PER_BLOCK 16    // 625 blocks, 2 nodes per warp

// ---------------- scratch (no allocation allowed) ----------------
// INVARIANT: g_cnt all-zero at entry; statically zero at load, and
// k_agg_gemm re-zeroes every counter it reads.
__device__ int   g_cnt[N_NODES * NREP];
__device__ int   g_srcs[N_NODES * NREP * CAP_R];
__device__ uint2 g_xh[N_NODES * 32];               // x in fp16

__device__ __forceinline__ void load4(const void* p, int t, int is64, int v[EPT]) {
    if (is64) {
        const longlong2* q = (const longlong2*)p;
        longlong2 w0 = q[t * 2];
        longlong2 w1 = q[t * 2 + 1];
        v[0] = (int)w0.x; v[1] = (int)w0.y;
        v[2] = (int)w1.x; v[3] = (int)w1.y;
    } else {
        const int4* q = (const int4*)p;
        int4 w = q[t];
        v[0] = w.x; v[1] = w.y; v[2] = w.z; v[3] = w.w;
    }
}

// merged front kernel: blocks [0,625) convert x -> fp16; blocks [625,1250) scatter
__global__ void k_front(const float4* __restrict__ x4,
                        const void* __restrict__ src,
                        const void* __restrict__ dst) {
    if (blockIdx.x < PREP_BLOCKS) {
        int i = blockIdx.x * blockDim.x + threadIdx.x;
        int a = i * 2, b = i * 2 + 1;
        if (b < N_NODES * 32) {
            float4 va = x4[a];
            float4 vb = x4[b];
            __half2 a0 = __floats2half2_rn(va.x, va.y);
            __half2 a1 = __floats2half2_rn(va.z, va.w);
            __half2 b0 = __floats2half2_rn(vb.x, vb.y);
            __half2 b1 = __floats2half2_rn(vb.z, vb.w);
            uint2 wa, wb;
            wa.x = *(unsigned int*)&a0; wa.y = *(unsigned int*)&a1;
            wb.x = *(unsigned int*)&b0; wb.y = *(unsigned int*)&b1;
            g_xh[a] = wa;
            g_xh[b] = wb;
        }
        return;
    }

    int t = (blockIdx.x - PREP_BLOCKS) * blockDim.x + threadIdx.x;
    if (t >= N_EDGES / EPT) return;

    const longlong2* sp = (const longlong2*)src;
    longlong2 q0 = sp[0];
    longlong2 q1 = sp[1];
    int is64 = ((unsigned long long)q0.x < N_NODES) &
               ((unsigned long long)q0.y < N_NODES) &
               ((unsigned long long)q1.x < N_NODES) &
               ((unsigned long long)q1.y < N_NODES);

    int s[EPT], d[EPT], pos[EPT], slot[EPT];
    load4(src, t, is64, s);
    load4(dst, t, is64, d);
    int rbase = (t & 1) << 2;
    #pragma unroll
    for (int k = 0; k < EPT; k++) {
        slot[k] = d[k] * NREP + (rbase | k);
        pos[k]  = atomicAdd(&g_cnt[slot[k]], 1);
    }
    #pragma unroll
    for (int k = 0; k < EPT; k++)
        if (pos[k] < CAP_R)
            g_srcs[slot[k] * CAP_R + pos[k]] = s[k];
}

// ---------------- fused aggregation + GEMM (16 nodes / block) ----------------
#define SW_STRIDE 36
#define SH_STRIDE 136

typedef unsigned long long u64;

// packed f32x2 accumulate: acc_pair += (float2)half2
__device__ __forceinline__ void acc_half4p(u64& a01, u64& a23, uint2 w) {
    __half2 h0 = *(__half2*)&w.x;
    __half2 h1 = *(__half2*)&w.y;
    float2 f0 = __half22float2(h0);
    float2 f1 = __half22float2(h1);
    u64 p0, p1;
    asm("mov.b64 %0, {%1,%2};" : "=l"(p0) : "f"(f0.x), "f"(f0.y));
    asm("mov.b64 %0, {%1,%2};" : "=l"(p1) : "f"(f1.x), "f"(f1.y));
    asm("add.rn.f32x2 %0, %0, %1;" : "+l"(a01) : "l"(p0));
    asm("add.rn.f32x2 %0, %0, %1;" : "+l"(a23) : "l"(p1));
}

__device__ __forceinline__ u64 packf2(float x, float y) {
    u64 p;
    asm("mov.b64 %0, {%1,%2};" : "=l"(p) : "f"(x), "f"(y));
    return p;
}
__device__ __forceinline__ void addf2(u64& a, u64 b) {
    asm("add.rn.f32x2 %0, %0, %1;" : "+l"(a) : "l"(b));
}
__device__ __forceinline__ float2 unpackf2(u64 p) {
    float2 f;
    asm("mov.b64 {%0,%1}, %2;" : "=f"(f.x), "=f"(f.y) : "l"(p));
    return f;
}

// fetch this chunk's per-lane bucket index (branchless select over 8 buckets)
__device__ __forceinline__ int fetch_chunk_idx(const int cnts[NREP], int slotbase,
                                               int pos, int total) {
    int myidx = 0;
    if (pos < total) {
        int run = 0, rb = 0, off = 0;
        #pragma unroll
        for (int b = 0; b < NREP; b++) {
            int nb = cnts[b];
            bool in = (pos >= run) & (pos < run + nb);
            if (in) { rb = b; off = pos - run; }
            run += nb;
        }
        myidx = g_srcs[slotbase + rb * CAP_R + off];
    }
    return myidx;
}

__global__ void __launch_bounds__(256, 4)
k_agg_gemm(const float4* __restrict__ x4,
           const float*  __restrict__ W,
           const float*  __restrict__ bias,
           float* __restrict__ out) {
    __shared__ float shW[128 * SW_STRIDE];
    __shared__ float shH[NODES_PER_BLOCK * SH_STRIDE];

    int tid  = threadIdx.x;
    int lane = tid & 31;
    int wrp  = tid >> 5;
    int row0 = blockIdx.x * NODES_PER_BLOCK;
    const unsigned FULL = 0xFFFFFFFFu;

    // ---- Phase A: each warp aggregates 2 nodes, pipelined chunk gather ----
    #pragma unroll 1
    for (int r = 0; r < 2; r++) {
        int node = row0 + wrp * 2 + r;

        float4 self = x4[node * F4 + lane];      // self term, fp32 exact
        // 4 accumulator chains x 2 packed-f32x2
        u64 A0 = packf2(self.x, self.y), A1 = packf2(self.z, self.w);
        u64 B0 = packf2(0.f, 0.f), B1 = packf2(0.f, 0.f);
        u64 C0 = packf2(0.f, 0.f), C1 = packf2(0.f, 0.f);
        u64 D0 = packf2(0.f, 0.f), D1 = packf2(0.f, 0.f);

        int4 c0 = *(const int4*)&g_cnt[node * NREP];
        int4 c1 = *(const int4*)&g_cnt[node * NREP + 4];
        if (lane < NREP) g_cnt[node * NREP + lane] = 0;   // reset for next replay

        int cnts[NREP] = {min(c0.x,CAP_R), min(c0.y,CAP_R), min(c0.z,CAP_R), min(c0.w,CAP_R),
                          min(c1.x,CAP_R), min(c1.y,CAP_R), min(c1.z,CAP_R), min(c1.w,CAP_R)};
        int total = 0;
        #pragma unroll
        for (int b = 0; b < NREP; b++) total += cnts[b];

        int slotbase = node * NREP * CAP_R;
        int nchunks = (total + 31) >> 5;

        int myidx = (nchunks > 0) ? fetch_chunk_idx(cnts, slotbase, lane, total) : 0;

        #pragma unroll 1
        for (int ch = 0; ch < nchunks; ch++) {
            int nextidx = 0;
            if (ch + 1 < nchunks)
                nextidx = fetch_chunk_idx(cnts, slotbase, ((ch + 1) << 5) + lane, total);

            int n = min(32, total - (ch << 5));
            int i = 0;
            for (; i + 8 <= n; i += 8) {
                int i0 = __shfl_sync(FULL, myidx, i);
                int i1 = __shfl_sync(FULL, myidx, i + 1);
                int i2 = __shfl_sync(FULL, myidx, i + 2);
                int i3 = __shfl_sync(FULL, myidx, i + 3);
                int i4 = __shfl_sync(FULL, myidx, i + 4);
                int i5 = __shfl_sync(FULL, myidx, i + 5);
                int i6 = __shfl_sync(FULL, myidx, i + 6);
                int i7 = __shfl_sync(FULL, myidx, i + 7);
                uint2 wa = g_xh[i0 * 32 + lane];
                uint2 wb = g_xh[i1 * 32 + lane];
                uint2 wc = g_xh[i2 * 32 + lane];
                uint2 wd = g_xh[i3 * 32 + lane];
                uint2 we = g_xh[i4 * 32 + lane];
                uint2 wf = g_xh[i5 * 32 + lane];
                uint2 wg = g_xh[i6 * 32 + lane];
                uint2 wh = g_xh[i7 * 32 + lane];
                acc_half4p(A0, A1, wa);
                acc_half4p(B0, B1, wb);
                acc_half4p(C0, C1, wc);
                acc_half4p(D0, D1, wd);
                acc_half4p(A0, A1, we);
                acc_half4p(B0, B1, wf);
                acc_half4p(C0, C1, wg);
                acc_half4p(D0, D1, wh);
            }
            for (; i + 4 <= n; i += 4) {
                int i0 = __shfl_sync(FULL, myidx, i);
                int i1 = __shfl_sync(FULL, myidx, i + 1);
                int i2 = __shfl_sync(FULL, myidx, i + 2);
                int i3 = __shfl_sync(FULL, myidx, i + 3);
                uint2 wa = g_xh[i0 * 32 + lane];
                uint2 wb = g_xh[i1 * 32 + lane];
                uint2 wc = g_xh[i2 * 32 + lane];
                uint2 wd = g_xh[i3 * 32 + lane];
                acc_half4p(A0, A1, wa);
                acc_half4p(B0, B1, wb);
                acc_half4p(C0, C1, wc);
                acc_half4p(D0, D1, wd);
            }
            for (; i < n; i++) {
                int ii = __shfl_sync(FULL, myidx, i);
                uint2 wa = g_xh[ii * 32 + lane];
                acc_half4p(A0, A1, wa);
            }
            myidx = nextidx;
        }
        addf2(A0, B0); addf2(A1, B1);
        addf2(C0, D0); addf2(C1, D1);
        addf2(A0, C0); addf2(A1, C1);
        float2 lo = unpackf2(A0);
        float2 hi = unpackf2(A1);
        *(float4*)&shH[(wrp * 2 + r) * SH_STRIDE + lane * 4] =
            make_float4(lo.x, lo.y, hi.x, hi.y);
    }
    __syncthreads();

    // ---- Phase B: GEMM 16x128 @ 128x128^T (fp32), 2x4 register tile ----
    float acc[2][4];
    #pragma unroll
    for (int i = 0; i < 2; i++)
        #pragma unroll
        for (int j = 0; j < 4; j++) acc[i][j] = 0.f;

    for (int kk = 0; kk < FEATS; kk += 32) {
        #pragma unroll
        for (int i = 0; i < 4; i++) {
            int t  = tid + i * 256;
            int rr = t >> 3;
            int c4 = (t & 7) * 4;
            float4 v = *(const float4*)&W[rr * FEATS + kk + c4];
            *(float4*)&shW[rr * SW_STRIDE + c4] = v;
        }
        __syncthreads();

        #pragma unroll
        for (int k4 = 0; k4 < 32; k4 += 4) {
            float4 ha[2], wb[4];
            #pragma unroll
            for (int ri = 0; ri < 2; ri++)
                ha[ri] = *(const float4*)&shH[(wrp * 2 + ri) * SH_STRIDE + kk + k4];
            #pragma unroll
            for (int ci = 0; ci < 4; ci++)
                wb[ci] = *(const float4*)&shW[(lane + 32 * ci) * SW_STRIDE + k4];
            #pragma unroll
            for (int ri = 0; ri < 2; ri++)
                #pragma unroll
                for (int ci = 0; ci < 4; ci++) {
                    acc[ri][ci] += ha[ri].x * wb[ci].x;
                    acc[ri][ci] += ha[ri].y * wb[ci].y;
                    acc[ri][ci] += ha[ri].z * wb[ci].z;
                    acc[ri][ci] += ha[ri].w * wb[ci].w;
                }
        }
        __syncthreads();
    }

    #pragma unroll
    for (int ri = 0; ri < 2; ri++) {
        int rr = row0 + wrp * 2 + ri;
        #pragma unroll
        for (int ci = 0; ci < 4; ci++) {
            int c = lane + 32 * ci;
            out[rr * FEATS + c] = acc[ri][ci] + bias[c];
        }
    }
}

// ---------------- launch ----------------
extern "C" void kernel_launch(void* const* d_in, const int* in_sizes, int n_in,
                              void* d_out, int out_size) {
    const float* x    = (const float*)d_in[0];
    const void*  src  = d_in[1];
    const void*  dst  = d_in[2];
    const float* W    = (const float*)d_in[3];
    const float* bias = (const float*)d_in[4];
    float* out = (float*)d_out;

    k_front<<<PREP_BLOCKS + SCAT_BLOCKS, 256>>>((const float4*)x, src, dst);
    k_agg_gemm<<<N_NODES / NODES_PER_BLOCK, 256>>>((const float4*)x, W, bias, out);
}

// round 10
// speedup vs baseline: 1.0976x; 1.0560x over previous
#include <cuda_runtime.h>
#include <cuda_fp16.h>
#include <cuda_bf16.h>

#define N_NODES   10000
#define N_EDGES   640000
#define FEATS     128
#define F4        (FEATS/4)
#define NREP      8           // counter replicas per node
#define CAP_R     40          // bucket capacity per replica
#define EPT       4           // edges per thread in scatter

#define PREP_BLOCKS 625
#define SCAT_BLOCKS 625
#define WCVT_BLOCKS 16        // 16*256*4 = 16384 = W elements

#define NODES_PER_BLOCK 16    // 625 blocks, 2 nodes per warp

// ---------------- scratch (no allocation allowed) ----------------
// INVARIANT: g_cnt all-zero at entry; statically zero at load, and
// k_agg_gemm re-zeroes every counter it reads.
__device__ int   g_cnt[N_NODES * NREP];
__device__ int   g_srcs[N_NODES * NREP * CAP_R];
__device__ uint2 g_xh[N_NODES * 32];               // x in fp16
__device__ float g_wt[FEATS * FEATS];              // W pre-rounded to tf32

typedef unsigned long long u64;

__device__ __forceinline__ unsigned f2tf32(float f) {
    unsigned r;
    asm("cvt.rna.tf32.f32 %0, %1;" : "=r"(r) : "f"(f));
    return r;
}

__device__ __forceinline__ void load4(const void* p, int t, int is64, int v[EPT]) {
    if (is64) {
        const longlong2* q = (const longlong2*)p;
        longlong2 w0 = q[t * 2];
        longlong2 w1 = q[t * 2 + 1];
        v[0] = (int)w0.x; v[1] = (int)w0.y;
        v[2] = (int)w1.x; v[3] = (int)w1.y;
    } else {
        const int4* q = (const int4*)p;
        int4 w = q[t];
        v[0] = w.x; v[1] = w.y; v[2] = w.z; v[3] = w.w;
    }
}

// merged front kernel:
//   blocks [0, 625)            : convert x -> fp16
//   blocks [625, 1250)         : bucketed edge scatter
//   blocks [1250, 1266)        : round W to tf32
__global__ void k_front(const float4* __restrict__ x4,
                        const void* __restrict__ src,
                        const void* __restrict__ dst,
                        const float* __restrict__ W) {
    if (blockIdx.x < PREP_BLOCKS) {
        int i = blockIdx.x * blockDim.x + threadIdx.x;
        int a = i * 2, b = i * 2 + 1;
        if (b < N_NODES * 32) {
            float4 va = x4[a];
            float4 vb = x4[b];
            __half2 a0 = __floats2half2_rn(va.x, va.y);
            __half2 a1 = __floats2half2_rn(va.z, va.w);
            __half2 b0 = __floats2half2_rn(vb.x, vb.y);
            __half2 b1 = __floats2half2_rn(vb.z, vb.w);
            uint2 wa, wb;
            wa.x = *(unsigned int*)&a0; wa.y = *(unsigned int*)&a1;
            wb.x = *(unsigned int*)&b0; wb.y = *(unsigned int*)&b1;
            g_xh[a] = wa;
            g_xh[b] = wb;
        }
        return;
    }
    if (blockIdx.x >= PREP_BLOCKS + SCAT_BLOCKS) {
        int i = (blockIdx.x - PREP_BLOCKS - SCAT_BLOCKS) * blockDim.x + threadIdx.x;
        float4 v = *(const float4*)&W[i * 4];
        uint4 o;
        o.x = f2tf32(v.x); o.y = f2tf32(v.y);
        o.z = f2tf32(v.z); o.w = f2tf32(v.w);
        *(uint4*)&g_wt[i * 4] = o;
        return;
    }

    int t = (blockIdx.x - PREP_BLOCKS) * blockDim.x + threadIdx.x;
    if (t >= N_EDGES / EPT) return;

    const longlong2* sp = (const longlong2*)src;
    longlong2 q0 = sp[0];
    longlong2 q1 = sp[1];
    int is64 = ((unsigned long long)q0.x < N_NODES) &
               ((unsigned long long)q0.y < N_NODES) &
               ((unsigned long long)q1.x < N_NODES) &
               ((unsigned long long)q1.y < N_NODES);

    int s[EPT], d[EPT], pos[EPT], slot[EPT];
    load4(src, t, is64, s);
    load4(dst, t, is64, d);
    int rbase = (t & 1) << 2;
    #pragma unroll
    for (int k = 0; k < EPT; k++) {
        slot[k] = d[k] * NREP + (rbase | k);
        pos[k]  = atomicAdd(&g_cnt[slot[k]], 1);
    }
    #pragma unroll
    for (int k = 0; k < EPT; k++)
        if (pos[k] < CAP_R)
            g_srcs[slot[k] * CAP_R + pos[k]] = s[k];
}

// ---------------- fused aggregation + tf32-MMA GEMM ----------------
#define SH_STRIDE 132   // words; conflict-free for mma A-frag LDS (132%32=4)

// packed f32x2 accumulate: acc_pair += (float2)half2
__device__ __forceinline__ void acc_half4p(u64& a01, u64& a23, uint2 w) {
    __half2 h0 = *(__half2*)&w.x;
    __half2 h1 = *(__half2*)&w.y;
    float2 f0 = __half22float2(h0);
    float2 f1 = __half22float2(h1);
    u64 p0, p1;
    asm("mov.b64 %0, {%1,%2};" : "=l"(p0) : "f"(f0.x), "f"(f0.y));
    asm("mov.b64 %0, {%1,%2};" : "=l"(p1) : "f"(f1.x), "f"(f1.y));
    asm("add.rn.f32x2 %0, %0, %1;" : "+l"(a01) : "l"(p0));
    asm("add.rn.f32x2 %0, %0, %1;" : "+l"(a23) : "l"(p1));
}
__device__ __forceinline__ u64 packf2(float x, float y) {
    u64 p;
    asm("mov.b64 %0, {%1,%2};" : "=l"(p) : "f"(x), "f"(y));
    return p;
}
__device__ __forceinline__ void addf2(u64& a, u64 b) {
    asm("add.rn.f32x2 %0, %0, %1;" : "+l"(a) : "l"(b));
}
__device__ __forceinline__ float2 unpackf2(u64 p) {
    float2 f;
    asm("mov.b64 {%0,%1}, %2;" : "=f"(f.x), "=f"(f.y) : "l"(p));
    return f;
}

__device__ __forceinline__ int fetch_chunk_idx(const int cnts[NREP], int slotbase,
                                               int pos, int total) {
    int myidx = 0;
    if (pos < total) {
        int run = 0, rb = 0, off = 0;
        #pragma unroll
        for (int b = 0; b < NREP; b++) {
            int nb = cnts[b];
            bool in = (pos >= run) & (pos < run + nb);
            if (in) { rb = b; off = pos - run; }
            run += nb;
        }
        myidx = g_srcs[slotbase + rb * CAP_R + off];
    }
    return myidx;
}

__global__ void __launch_bounds__(256, 4)
k_agg_gemm(const float4* __restrict__ x4,
           const float*  __restrict__ bias,
           float* __restrict__ out) {
    __shared__ float shH[NODES_PER_BLOCK * SH_STRIDE];   // 8.4 KB, tf32-rounded h

    int tid  = threadIdx.x;
    int lane = tid & 31;
    int wrp  = tid >> 5;
    int row0 = blockIdx.x * NODES_PER_BLOCK;
    const unsigned FULL = 0xFFFFFFFFu;

    // ---- Phase A: each warp aggregates 2 nodes, pipelined chunk gather ----
    #pragma unroll 1
    for (int r = 0; r < 2; r++) {
        int node = row0 + wrp * 2 + r;

        float4 self = x4[node * F4 + lane];      // self term, fp32 exact
        u64 A0 = packf2(self.x, self.y), A1 = packf2(self.z, self.w);
        u64 B0 = packf2(0.f, 0.f), B1 = packf2(0.f, 0.f);
        u64 C0 = packf2(0.f, 0.f), C1 = packf2(0.f, 0.f);
        u64 D0 = packf2(0.f, 0.f), D1 = packf2(0.f, 0.f);

        int4 c0 = *(const int4*)&g_cnt[node * NREP];
        int4 c1 = *(const int4*)&g_cnt[node * NREP + 4];
        if (lane < NREP) g_cnt[node * NREP + lane] = 0;   // reset for next replay

        int cnts[NREP] = {min(c0.x,CAP_R), min(c0.y,CAP_R), min(c0.z,CAP_R), min(c0.w,CAP_R),
                          min(c1.x,CAP_R), min(c1.y,CAP_R), min(c1.z,CAP_R), min(c1.w,CAP_R)};
        int total = 0;
        #pragma unroll
        for (int b = 0; b < NREP; b++) total += cnts[b];

        int slotbase = node * NREP * CAP_R;
        int nchunks = (total + 31) >> 5;

        int myidx = (nchunks > 0) ? fetch_chunk_idx(cnts, slotbase, lane, total) : 0;

        #pragma unroll 1
        for (int ch = 0; ch < nchunks; ch++) {
            int nextidx = 0;
            if (ch + 1 < nchunks)
                nextidx = fetch_chunk_idx(cnts, slotbase, ((ch + 1) << 5) + lane, total);

            int n = min(32, total - (ch << 5));
            int i = 0;
            for (; i + 8 <= n; i += 8) {
                int i0 = __shfl_sync(FULL, myidx, i);
                int i1 = __shfl_sync(FULL, myidx, i + 1);
                int i2 = __shfl_sync(FULL, myidx, i + 2);
                int i3 = __shfl_sync(FULL, myidx, i + 3);
                int i4 = __shfl_sync(FULL, myidx, i + 4);
                int i5 = __shfl_sync(FULL, myidx, i + 5);
                int i6 = __shfl_sync(FULL, myidx, i + 6);
                int i7 = __shfl_sync(FULL, myidx, i + 7);
                uint2 wa = g_xh[i0 * 32 + lane];
                uint2 wb = g_xh[i1 * 32 + lane];
                uint2 wc = g_xh[i2 * 32 + lane];
                uint2 wd = g_xh[i3 * 32 + lane];
                uint2 we = g_xh[i4 * 32 + lane];
                uint2 wf = g_xh[i5 * 32 + lane];
                uint2 wg = g_xh[i6 * 32 + lane];
                uint2 wh = g_xh[i7 * 32 + lane];
                acc_half4p(A0, A1, wa);
                acc_half4p(B0, B1, wb);
                acc_half4p(C0, C1, wc);
                acc_half4p(D0, D1, wd);
                acc_half4p(A0, A1, we);
                acc_half4p(B0, B1, wf);
                acc_half4p(C0, C1, wg);
                acc_half4p(D0, D1, wh);
            }
            for (; i + 4 <= n; i += 4) {
                int i0 = __shfl_sync(FULL, myidx, i);
                int i1 = __shfl_sync(FULL, myidx, i + 1);
                int i2 = __shfl_sync(FULL, myidx, i + 2);
                int i3 = __shfl_sync(FULL, myidx, i + 3);
                uint2 wa = g_xh[i0 * 32 + lane];
                uint2 wb = g_xh[i1 * 32 + lane];
                uint2 wc = g_xh[i2 * 32 + lane];
                uint2 wd = g_xh[i3 * 32 + lane];
                acc_half4p(A0, A1, wa);
                acc_half4p(B0, B1, wb);
                acc_half4p(C0, C1, wc);
                acc_half4p(D0, D1, wd);
            }
            for (; i < n; i++) {
                int ii = __shfl_sync(FULL, myidx, i);
                uint2 wa = g_xh[ii * 32 + lane];
                acc_half4p(A0, A1, wa);
            }
            myidx = nextidx;
        }
        addf2(A0, B0); addf2(A1, B1);
        addf2(C0, D0); addf2(C1, D1);
        addf2(A0, C0); addf2(A1, C1);
        float2 lo = unpackf2(A0);
        float2 hi = unpackf2(A1);
        // store tf32-rounded h (A operand of the MMA)
        uint4 o;
        o.x = f2tf32(lo.x); o.y = f2tf32(lo.y);
        o.z = f2tf32(hi.x); o.w = f2tf32(hi.y);
        *(uint4*)&shH[(wrp * 2 + r) * SH_STRIDE + lane * 4] = o;
    }
    __syncthreads();

    // ---- Phase B: out = shH(16x128) @ W^T via mma.sync m16n8k8 tf32 ----
    // warp wrp covers output cols [16*wrp, 16*wrp+16) as two n8 tiles.
    {
        int g = lane >> 2;        // groupID
        int c = lane & 3;         // thread-in-group
        int n0 = wrp * 16;

        float acc[2][4];
        #pragma unroll
        for (int nt = 0; nt < 2; nt++)
            #pragma unroll
            for (int j = 0; j < 4; j++) acc[nt][j] = 0.f;

        #pragma unroll
        for (int kt = 0; kt < 16; kt++) {
            int k0 = kt * 8;
            unsigned a0 = __float_as_uint(shH[g * SH_STRIDE + k0 + c]);
            unsigned a1 = __float_as_uint(shH[(g + 8) * SH_STRIDE + k0 + c]);
            unsigned a2 = __float_as_uint(shH[g * SH_STRIDE + k0 + c + 4]);
            unsigned a3 = __float_as_uint(shH[(g + 8) * SH_STRIDE + k0 + c + 4]);
            #pragma unroll
            for (int nt = 0; nt < 2; nt++) {
                int nrow = n0 + nt * 8 + g;
                unsigned b0 = __float_as_uint(g_wt[nrow * FEATS + k0 + c]);
                unsigned b1 = __float_as_uint(g_wt[nrow * FEATS + k0 + c + 4]);
                asm volatile(
                    "mma.sync.aligned.m16n8k8.row.col.f32.tf32.tf32.f32 "
                    "{%0,%1,%2,%3}, {%4,%5,%6,%7}, {%8,%9}, {%0,%1,%2,%3};"
                    : "+f"(acc[nt][0]), "+f"(acc[nt][1]),
                      "+f"(acc[nt][2]), "+f"(acc[nt][3])
                    : "r"(a0), "r"(a1), "r"(a2), "r"(a3), "r"(b0), "r"(b1));
            }
        }

        #pragma unroll
        for (int nt = 0; nt < 2; nt++) {
            int colb = n0 + nt * 8 + 2 * c;
            float2 bv = *(const float2*)&bias[colb];
            float2 o0 = make_float2(acc[nt][0] + bv.x, acc[nt][1] + bv.y);
            float2 o1 = make_float2(acc[nt][2] + bv.x, acc[nt][3] + bv.y);
            *(float2*)&out[(row0 + g) * FEATS + colb]     = o0;
            *(float2*)&out[(row0 + g + 8) * FEATS + colb] = o1;
        }
    }
}

// ---------------- launch ----------------
extern "C" void kernel_launch(void* const* d_in, const int* in_sizes, int n_in,
                              void* d_out, int out_size) {
    const float* x    = (const float*)d_in[0];
    const void*  src  = d_in[1];
    const void*  dst  = d_in[2];
    const float* W    = (const float*)d_in[3];
    const float* bias = (const float*)d_in[4];
    float* out = (float*)d_out;

    k_front<<<PREP_BLOCKS + SCAT_BLOCKS + WCVT_BLOCKS, 256>>>((const float4*)x, src, dst, W);
    k_agg_gemm<<<N_NODES / NODES_PER_BLOCK, 256>>>((const float4*)x, bias, out);
}

// round 11
// speedup vs baseline: 1.1492x; 1.0470x over previous
#include <cuda_runtime.h>
#include <cuda_fp16.h>
#include <cuda_bf16.h>

#define N_NODES   10000
#define N_EDGES   640000
#define FEATS     128
#define F4        (FEATS/4)
#define NREP      8
#define CAP_R     40
#define EPT       4

#define PREP_BLOCKS 625
#define SCAT_BLOCKS 625
#define WCVT_BLOCKS 16

#define NODES_PER_BLOCK 16    // 625 blocks, 2 nodes per warp

// INVARIANT: g_cnt all-zero at entry; statically zero at load, and
// k_agg_gemm re-zeroes every counter it reads.
__device__ int   g_cnt[N_NODES * NREP];
__device__ int   g_srcs[N_NODES * NREP * CAP_R];
__device__ uint2 g_xh[N_NODES * 32];               // x in fp16
__device__ float g_wt[FEATS * FEATS];              // W pre-rounded to tf32

typedef unsigned long long u64;

__device__ __forceinline__ unsigned f2tf32(float f) {
    unsigned r;
    asm("cvt.rna.tf32.f32 %0, %1;" : "=r"(r) : "f"(f));
    return r;
}

__device__ __forceinline__ void load4(const void* p, int t, int is64, int v[EPT]) {
    if (is64) {
        const longlong2* q = (const longlong2*)p;
        longlong2 w0 = q[t * 2];
        longlong2 w1 = q[t * 2 + 1];
        v[0] = (int)w0.x; v[1] = (int)w0.y;
        v[2] = (int)w1.x; v[3] = (int)w1.y;
    } else {
        const int4* q = (const int4*)p;
        int4 w = q[t];
        v[0] = w.x; v[1] = w.y; v[2] = w.z; v[3] = w.w;
    }
}

// merged front kernel: [0,625) x->fp16; [625,1250) scatter; [1250,1266) W->tf32
__global__ void k_front(const float4* __restrict__ x4,
                        const void* __restrict__ src,
                        const void* __restrict__ dst,
                        const float* __restrict__ W) {
    if (blockIdx.x < PREP_BLOCKS) {
        int i = blockIdx.x * blockDim.x + threadIdx.x;
        int a = i * 2, b = i * 2 + 1;
        if (b < N_NODES * 32) {
            float4 va = x4[a];
            float4 vb = x4[b];
            __half2 a0 = __floats2half2_rn(va.x, va.y);
            __half2 a1 = __floats2half2_rn(va.z, va.w);
            __half2 b0 = __floats2half2_rn(vb.x, vb.y);
            __half2 b1 = __floats2half2_rn(vb.z, vb.w);
            uint2 wa, wb;
            wa.x = *(unsigned int*)&a0; wa.y = *(unsigned int*)&a1;
            wb.x = *(unsigned int*)&b0; wb.y = *(unsigned int*)&b1;
            g_xh[a] = wa;
            g_xh[b] = wb;
        }
        return;
    }
    if (blockIdx.x >= PREP_BLOCKS + SCAT_BLOCKS) {
        int i = (blockIdx.x - PREP_BLOCKS - SCAT_BLOCKS) * blockDim.x + threadIdx.x;
        float4 v = *(const float4*)&W[i * 4];
        uint4 o;
        o.x = f2tf32(v.x); o.y = f2tf32(v.y);
        o.z = f2tf32(v.z); o.w = f2tf32(v.w);
        *(uint4*)&g_wt[i * 4] = o;
        return;
    }

    int t = (blockIdx.x - PREP_BLOCKS) * blockDim.x + threadIdx.x;
    if (t >= N_EDGES / EPT) return;

    const longlong2* sp = (const longlong2*)src;
    longlong2 q0 = sp[0];
    longlong2 q1 = sp[1];
    int is64 = ((unsigned long long)q0.x < N_NODES) &
               ((unsigned long long)q0.y < N_NODES) &
               ((unsigned long long)q1.x < N_NODES) &
               ((unsigned long long)q1.y < N_NODES);

    int s[EPT], d[EPT], pos[EPT], slot[EPT];
    load4(src, t, is64, s);
    load4(dst, t, is64, d);
    int rbase = (t & 1) << 2;
    #pragma unroll
    for (int k = 0; k < EPT; k++) {
        slot[k] = d[k] * NREP + (rbase | k);
        pos[k]  = atomicAdd(&g_cnt[slot[k]], 1);
    }
    #pragma unroll
    for (int k = 0; k < EPT; k++)
        if (pos[k] < CAP_R)
            g_srcs[slot[k] * CAP_R + pos[k]] = s[k];
}

// ---------------- fused aggregation + tf32-MMA GEMM ----------------
#define SH_STRIDE 132

__device__ __forceinline__ u64 packf2(float x, float y) {
    u64 p;
    asm("mov.b64 %0, {%1,%2};" : "=l"(p) : "f"(x), "f"(y));
    return p;
}
__device__ __forceinline__ void addf2(u64& a, u64 b) {
    asm("add.rn.f32x2 %0, %0, %1;" : "+l"(a) : "l"(b));
}
__device__ __forceinline__ float2 unpackf2(u64 p) {
    float2 f;
    asm("mov.b64 {%0,%1}, %2;" : "=f"(f.x), "=f"(f.y) : "l"(p));
    return f;
}

// single-edge accumulate (remainder path)
__device__ __forceinline__ void acc_one(u64& a01, u64& a23, uint2 w) {
    float2 f0 = __half22float2(*(__half2*)&w.x);
    float2 f1 = __half22float2(*(__half2*)&w.y);
    addf2(a01, packf2(f0.x, f0.y));
    addf2(a23, packf2(f1.x, f1.y));
}

// pair accumulate: fp16 pre-add (1 extra fp16 rounding), then one f32 add
__device__ __forceinline__ void acc_pair(u64& a01, u64& a23, uint2 wa, uint2 wb) {
    __half2 p0 = __hadd2(*(__half2*)&wa.x, *(__half2*)&wb.x);
    __half2 p1 = __hadd2(*(__half2*)&wa.y, *(__half2*)&wb.y);
    float2 f0 = __half22float2(p0);
    float2 f1 = __half22float2(p1);
    addf2(a01, packf2(f0.x, f0.y));
    addf2(a23, packf2(f1.x, f1.y));
}

__device__ __forceinline__ int fetch_chunk_idx(const int cnts[NREP], int slotbase,
                                               int pos, int total) {
    int myidx = 0;
    if (pos < total) {
        int run = 0, rb = 0, off = 0;
        #pragma unroll
        for (int b = 0; b < NREP; b++) {
            int nb = cnts[b];
            bool in = (pos >= run) & (pos < run + nb);
            if (in) { rb = b; off = pos - run; }
            run += nb;
        }
        myidx = g_srcs[slotbase + rb * CAP_R + off];
    }
    return myidx;
}

__global__ void __launch_bounds__(256, 5)
k_agg_gemm(const float4* __restrict__ x4,
           const float*  __restrict__ bias,
           float* __restrict__ out) {
    __shared__ float shH[NODES_PER_BLOCK * SH_STRIDE];   // 8.4 KB

    int tid  = threadIdx.x;
    int lane = tid & 31;
    int wrp  = tid >> 5;
    int row0 = blockIdx.x * NODES_PER_BLOCK;
    const unsigned FULL = 0xFFFFFFFFu;

    // ---- Phase A: each warp aggregates 2 nodes, pipelined chunk gather ----
    #pragma unroll 1
    for (int r = 0; r < 2; r++) {
        int node = row0 + wrp * 2 + r;

        float4 self = x4[node * F4 + lane];
        u64 A0 = packf2(self.x, self.y), A1 = packf2(self.z, self.w);
        u64 B0 = packf2(0.f, 0.f),      B1 = packf2(0.f, 0.f);

        int4 c0 = *(const int4*)&g_cnt[node * NREP];
        int4 c1 = *(const int4*)&g_cnt[node * NREP + 4];
        if (lane < NREP) g_cnt[node * NREP + lane] = 0;   // reset for next replay

        int cnts[NREP] = {min(c0.x,CAP_R), min(c0.y,CAP_R), min(c0.z,CAP_R), min(c0.w,CAP_R),
                          min(c1.x,CAP_R), min(c1.y,CAP_R), min(c1.z,CAP_R), min(c1.w,CAP_R)};
        int total = 0;
        #pragma unroll
        for (int b = 0; b < NREP; b++) total += cnts[b];

        int slotbase = node * NREP * CAP_R;
        int nchunks = (total + 31) >> 5;

        int myidx = (nchunks > 0) ? fetch_chunk_idx(cnts, slotbase, lane, total) : 0;

        #pragma unroll 1
        for (int ch = 0; ch < nchunks; ch++) {
            int nextidx = 0;
            if (ch + 1 < nchunks)
                nextidx = fetch_chunk_idx(cnts, slotbase, ((ch + 1) << 5) + lane, total);

            int n = min(32, total - (ch << 5));
            int i = 0;
            for (; i + 8 <= n; i += 8) {
                int i0 = __shfl_sync(FULL, myidx, i);
                int i1 = __shfl_sync(FULL, myidx, i + 1);
                int i2 = __shfl_sync(FULL, myidx, i + 2);
                int i3 = __shfl_sync(FULL, myidx, i + 3);
                int i4 = __shfl_sync(FULL, myidx, i + 4);
                int i5 = __shfl_sync(FULL, myidx, i + 5);
                int i6 = __shfl_sync(FULL, myidx, i + 6);
                int i7 = __shfl_sync(FULL, myidx, i + 7);
                uint2 wa = g_xh[i0 * 32 + lane];
                uint2 wb = g_xh[i1 * 32 + lane];
                uint2 wc = g_xh[i2 * 32 + lane];
                uint2 wd = g_xh[i3 * 32 + lane];
                uint2 we = g_xh[i4 * 32 + lane];
                uint2 wf = g_xh[i5 * 32 + lane];
                uint2 wg = g_xh[i6 * 32 + lane];
                uint2 wh = g_xh[i7 * 32 + lane];
                acc_pair(A0, A1, wa, wb);
                acc_pair(B0, B1, wc, wd);
                acc_pair(A0, A1, we, wf);
                acc_pair(B0, B1, wg, wh);
            }
            for (; i + 2 <= n; i += 2) {
                int i0 = __shfl_sync(FULL, myidx, i);
                int i1 = __shfl_sync(FULL, myidx, i + 1);
                uint2 wa = g_xh[i0 * 32 + lane];
                uint2 wb = g_xh[i1 * 32 + lane];
                acc_pair(A0, A1, wa, wb);
            }
            for (; i < n; i++) {
                int ii = __shfl_sync(FULL, myidx, i);
                uint2 wa = g_xh[ii * 32 + lane];
                acc_one(B0, B1, wa);
            }
            myidx = nextidx;
        }
        addf2(A0, B0); addf2(A1, B1);
        float2 lo = unpackf2(A0);
        float2 hi = unpackf2(A1);
        uint4 o;
        o.x = f2tf32(lo.x); o.y = f2tf32(lo.y);
        o.z = f2tf32(hi.x); o.w = f2tf32(hi.y);
        *(uint4*)&shH[(wrp * 2 + r) * SH_STRIDE + lane * 4] = o;
    }
    __syncthreads();

    // ---- Phase B: out = shH(16x128) @ W^T via mma.sync m16n8k8 tf32 ----
    {
        int g = lane >> 2;
        int c = lane & 3;
        int n0 = wrp * 16;

        float acc[2][4];
        #pragma unroll
        for (int nt = 0; nt < 2; nt++)
            #pragma unroll
            for (int j = 0; j < 4; j++) acc[nt][j] = 0.f;

        #pragma unroll
        for (int kt = 0; kt < 16; kt++) {
            int k0 = kt * 8;
            unsigned a0 = __float_as_uint(shH[g * SH_STRIDE + k0 + c]);
            unsigned a1 = __float_as_uint(shH[(g + 8) * SH_STRIDE + k0 + c]);
            unsigned a2 = __float_as_uint(shH[g * SH_STRIDE + k0 + c + 4]);
            unsigned a3 = __float_as_uint(shH[(g + 8) * SH_STRIDE + k0 + c + 4]);
            #pragma unroll
            for (int nt = 0; nt < 2; nt++) {
                int nrow = n0 + nt * 8 + g;
                unsigned b0 = __float_as_uint(g_wt[nrow * FEATS + k0 + c]);
                unsigned b1 = __float_as_uint(g_wt[nrow * FEATS + k0 + c + 4]);
                asm volatile(
                    "mma.sync.aligned.m16n8k8.row.col.f32.tf32.tf32.f32 "
                    "{%0,%1,%2,%3}, {%4,%5,%6,%7}, {%8,%9}, {%0,%1,%2,%3};"
                    : "+f"(acc[nt][0]), "+f"(acc[nt][1]),
                      "+f"(acc[nt][2]), "+f"(acc[nt][3])
                    : "r"(a0), "r"(a1), "r"(a2), "r"(a3), "r"(b0), "r"(b1));
            }
        }

        #pragma unroll
        for (int nt = 0; nt < 2; nt++) {
            int colb = n0 + nt * 8 + 2 * c;
            float2 bv = *(const float2*)&bias[colb];
            float2 o0 = make_float2(acc[nt][0] + bv.x, acc[nt][1] + bv.y);
            float2 o1 = make_float2(acc[nt][2] + bv.x, acc[nt][3] + bv.y);
            *(float2*)&out[(row0 + g) * FEATS + colb]     = o0;
            *(float2*)&out[(row0 + g + 8) * FEATS + colb] = o1;
        }
    }
}

// ---------------- launch ----------------
extern "C" void kernel_launch(void* const* d_in, const int* in_sizes, int n_in,
                              void* d_out, int out_size) {
    const float* x    = (const float*)d_in[0];
    const void*  src  = d_in[1];
    const void*  dst  = d_in[2];
    const float* W    = (const float*)d_in[3];
    const float* bias = (const float*)d_in[4];
    float* out = (float*)d_out;

    k_front<<<PREP_BLOCKS + SCAT_BLOCKS + WCVT_BLOCKS, 256>>>((const float4*)x, src, dst, W);
    k_agg_gemm<<<N_NODES / NODES_PER_BLOCK, 256>>>((const float4*)x, bias, out);
}